// round 1
// baseline (speedup 1.0000x reference)
#include <cuda_runtime.h>

// Problem constants
// x: [8,2048,1024] fp32 -> 16384 token rows, groups of 16 consecutive tokens (G=1024)
// controller: [1024,16,4] -> ctrl[d*64 + es]
// f1: [1024,16,4,64]      -> f1[d*4096 + es*64 + f]
// f2: [16,4,64,1024]      -> f2[es*65536 + f*1024 + d]
// bias: [16,4,64]         -> bias[es*64 + f]
// out: [8,2048,1024] fp32

#define AP 70   // smem pitch (floats): conflict-free LDS.64 for 16-row-spread reads

__device__ int g_sel[1024 * 64];   // selected token (0..15) per (group, es)

__device__ __forceinline__ unsigned long long ffma2(unsigned long long a,
                                                    unsigned long long b,
                                                    unsigned long long c) {
    unsigned long long d;
    asm("fma.rn.f32x2 %0, %1, %2, %3;" : "=l"(d) : "l"(a), "l"(b), "l"(c));
    return d;
}

__device__ __forceinline__ float2 unpack2(unsigned long long v) {
    float2 r;
    asm("mov.b64 {%0, %1}, %2;" : "=f"(r.x), "=f"(r.y) : "l"(v));
    return r;
}

// ---------------------------------------------------------------------------
// Kernel 0: zero the output (it is poisoned; atomics need a zero base)
// ---------------------------------------------------------------------------
__global__ void k_zero(float4* __restrict__ out, int n4) {
    int i = blockIdx.x * blockDim.x + threadIdx.x;
    int stride = gridDim.x * blockDim.x;
    for (; i < n4; i += stride) out[i] = make_float4(0.f, 0.f, 0.f, 0.f);
}

// ---------------------------------------------------------------------------
// Kernel 1: router logits GEMM + per-(group,es) argmax over 16 tokens.
// Block: 256 threads, handles 64 token rows (4 groups) x 64 es, K=1024.
// Thread (rt,ct): rows {rt+16i}, cols {ct+16j} -> the 16 lanes of a cluster
// (same ct) hold the 16 tokens of each group -> shfl.bfly argmax.
// ---------------------------------------------------------------------------
__global__ __launch_bounds__(256) void k_router(const float* __restrict__ x,
                                                const float* __restrict__ ctrl) {
    __shared__ __align__(16) float As[64 * AP];  // [row][k]
    __shared__ __align__(16) float Bs[64 * AP];  // [es][k] (transposed)
    const int tid = threadIdx.x;
    const int rt = tid & 15;
    const int ct = tid >> 4;
    const int m0 = blockIdx.x * 64;

    unsigned long long acc[4][4];
#pragma unroll
    for (int i = 0; i < 4; i++)
#pragma unroll
        for (int j = 0; j < 4; j++) acc[i][j] = 0ull;

    for (int kc = 0; kc < 1024; kc += 64) {
        // A: x rows m0..m0+63, k-chunk, row-major (k contiguous)
#pragma unroll
        for (int q = 0; q < 4; q++) {
            int id = tid + 256 * q;
            int r = id >> 4;
            int k4 = (id & 15) << 2;
            float4 v = *(const float4*)(x + (m0 + r) * 1024 + kc + k4);
            float* dst = As + r * AP + k4;
            *(float2*)dst = make_float2(v.x, v.y);
            *(float2*)(dst + 2) = make_float2(v.z, v.w);
        }
        // B: transpose ctrl chunk -> Bs[es][k]
#pragma unroll
        for (int q = 0; q < 4; q++) {
            int id = tid + 256 * q;
            int k = id >> 4;
            int e4 = (id & 15) << 2;
            float4 v = *(const float4*)(ctrl + (kc + k) * 64 + e4);
            Bs[(e4 + 0) * AP + k] = v.x;
            Bs[(e4 + 1) * AP + k] = v.y;
            Bs[(e4 + 2) * AP + k] = v.z;
            Bs[(e4 + 3) * AP + k] = v.w;
        }
        __syncthreads();
#pragma unroll
        for (int k = 0; k < 64; k += 2) {
            unsigned long long a[4], b[4];
#pragma unroll
            for (int i = 0; i < 4; i++)
                a[i] = *(const unsigned long long*)(As + (rt + 16 * i) * AP + k);
#pragma unroll
            for (int j = 0; j < 4; j++)
                b[j] = *(const unsigned long long*)(Bs + (ct + 16 * j) * AP + k);
#pragma unroll
            for (int i = 0; i < 4; i++)
#pragma unroll
                for (int j = 0; j < 4; j++) acc[i][j] = ffma2(a[i], b[j], acc[i][j]);
        }
        __syncthreads();
    }

    // tie-break identical to reference: + linspace(0, 1e-6, 16)[t]
    const float tie = (float)((double)rt * (1e-6 / 15.0));
#pragma unroll
    for (int i = 0; i < 4; i++) {
#pragma unroll
        for (int j = 0; j < 4; j++) {
            float2 p = unpack2(acc[i][j]);
            float v = p.x + p.y + tie;
            int t = rt;
#pragma unroll
            for (int m = 8; m >= 1; m >>= 1) {
                float ov = __shfl_xor_sync(0xffffffffu, v, m);
                int ot = __shfl_xor_sync(0xffffffffu, t, m);
                if (ov > v || (ov == v && ot > t)) { v = ov; t = ot; }
            }
            if (rt == 0) g_sel[(blockIdx.x * 4 + i) * 64 + (ct + 16 * j)] = t;
        }
    }
}

// ---------------------------------------------------------------------------
// Kernel 2: per-(es, mtile) fused FFN.
// Phase 1: H[64g x 64f] = relu(Xsel[64g x 1024] @ W1_es + b_es)
// Phase 2: Z[64g x 1024] = H @ W2_es, scatter-add to out via coalesced atomics
// ---------------------------------------------------------------------------
__global__ __launch_bounds__(256) void k_ffn(const float* __restrict__ x,
                                             const float* __restrict__ f1,
                                             const float* __restrict__ f2,
                                             const float* __restrict__ bias,
                                             float* __restrict__ out) {
    __shared__ __align__(16) float As[64 * AP];  // phase1: Xsel[g][k]; then H[g][f]
    __shared__ __align__(16) float Bs[64 * AP];  // phase1: W1[f][k]; phase2: W2[n][k] / Z stage
    __shared__ int selrow[64];                   // global token row per group
    const int tid = threadIdx.x;
    const int rt = tid & 15;
    const int ct = tid >> 4;
    const int g0 = blockIdx.x * 64;
    const int es = blockIdx.y;

    if (tid < 64) {
        int t = g_sel[(g0 + tid) * 64 + es];
        selrow[tid] = (g0 + tid) * 16 + t;
    }
    __syncthreads();

    unsigned long long acc[4][4];
#pragma unroll
    for (int i = 0; i < 4; i++)
#pragma unroll
        for (int j = 0; j < 4; j++) acc[i][j] = 0ull;

    // ---- Phase 1: gathered GEMM, M=64 N=64 K=1024 ----
    for (int kc = 0; kc < 1024; kc += 64) {
#pragma unroll
        for (int q = 0; q < 4; q++) {
            int id = tid + 256 * q;
            int r = id >> 4;
            int k4 = (id & 15) << 2;
            float4 v = *(const float4*)(x + selrow[r] * 1024 + kc + k4);
            float* dst = As + r * AP + k4;
            *(float2*)dst = make_float2(v.x, v.y);
            *(float2*)(dst + 2) = make_float2(v.z, v.w);
        }
#pragma unroll
        for (int q = 0; q < 4; q++) {
            int id = tid + 256 * q;
            int k = id >> 4;
            int fq = (id & 15) << 2;
            float4 v = *(const float4*)(f1 + (kc + k) * 4096 + es * 64 + fq);
            Bs[(fq + 0) * AP + k] = v.x;
            Bs[(fq + 1) * AP + k] = v.y;
            Bs[(fq + 2) * AP + k] = v.z;
            Bs[(fq + 3) * AP + k] = v.w;
        }
        __syncthreads();
#pragma unroll
        for (int k = 0; k < 64; k += 2) {
            unsigned long long a[4], b[4];
#pragma unroll
            for (int i = 0; i < 4; i++)
                a[i] = *(const unsigned long long*)(As + (rt + 16 * i) * AP + k);
#pragma unroll
            for (int j = 0; j < 4; j++)
                b[j] = *(const unsigned long long*)(Bs + (ct + 16 * j) * AP + k);
#pragma unroll
            for (int i = 0; i < 4; i++)
#pragma unroll
                for (int j = 0; j < 4; j++) acc[i][j] = ffma2(a[i], b[j], acc[i][j]);
        }
        __syncthreads();
    }

    // Phase 1 epilogue: bias + relu -> H into As (safe: past the last sync)
#pragma unroll
    for (int i = 0; i < 4; i++) {
#pragma unroll
        for (int j = 0; j < 4; j++) {
            float2 p = unpack2(acc[i][j]);
            int f = ct + 16 * j;
            float h = p.x + p.y + bias[es * 64 + f];
            As[(rt + 16 * i) * AP + f] = fmaxf(h, 0.0f);
        }
    }
    __syncthreads();

    // ---- Phase 2: Z = H @ W2, N=1024 in 16 chunks of 64, K=64 ----
    for (int nc = 0; nc < 16; nc++) {
#pragma unroll
        for (int q = 0; q < 4; q++) {
            int id = tid + 256 * q;
            int k = id >> 4;                       // f index
            int n4 = (id & 15) << 2;
            float4 v = *(const float4*)(f2 + es * 65536 + k * 1024 + nc * 64 + n4);
            Bs[(n4 + 0) * AP + k] = v.x;
            Bs[(n4 + 1) * AP + k] = v.y;
            Bs[(n4 + 2) * AP + k] = v.z;
            Bs[(n4 + 3) * AP + k] = v.w;
        }
        __syncthreads();

        unsigned long long acc2[4][4];
#pragma unroll
        for (int i = 0; i < 4; i++)
#pragma unroll
            for (int j = 0; j < 4; j++) acc2[i][j] = 0ull;
#pragma unroll
        for (int k = 0; k < 64; k += 2) {
            unsigned long long a[4], b[4];
#pragma unroll
            for (int i = 0; i < 4; i++)
                a[i] = *(const unsigned long long*)(As + (rt + 16 * i) * AP + k);
#pragma unroll
            for (int j = 0; j < 4; j++)
                b[j] = *(const unsigned long long*)(Bs + (ct + 16 * j) * AP + k);
#pragma unroll
            for (int i = 0; i < 4; i++)
#pragma unroll
                for (int j = 0; j < 4; j++) acc2[i][j] = ffma2(a[i], b[j], acc2[i][j]);
        }
        __syncthreads();   // done reading Bs(W2) -> reuse as Z stage

        // Stage Z in smem (pitch 66: conflict-free scatter store), then
        // coalesced atomicAdd (warps write 128B-contiguous runs).
#pragma unroll
        for (int i = 0; i < 4; i++)
#pragma unroll
            for (int j = 0; j < 4; j++) {
                float2 p = unpack2(acc2[i][j]);
                Bs[(rt + 16 * i) * 66 + (ct + 16 * j)] = p.x + p.y;
            }
        __syncthreads();
#pragma unroll
        for (int q = 0; q < 16; q++) {
            int idx = tid + 256 * q;
            int r = idx >> 6;
            int c = idx & 63;
            atomicAdd(out + selrow[r] * 1024 + nc * 64 + c, Bs[r * 66 + c]);
        }
        __syncthreads();   // before next chunk overwrites Bs
    }
}

// ---------------------------------------------------------------------------
extern "C" void kernel_launch(void* const* d_in, const int* in_sizes, int n_in,
                              void* d_out, int out_size) {
    const float* x    = (const float*)d_in[0];
    const float* ctrl = (const float*)d_in[1];
    const float* f1   = (const float*)d_in[2];
    const float* f2   = (const float*)d_in[3];
    const float* bias = (const float*)d_in[4];
    float* out = (float*)d_out;

    k_zero<<<2048, 256>>>((float4*)out, out_size / 4);
    k_router<<<256, 256>>>(x, ctrl);
    k_ffn<<<dim3(16, 64), 256>>>(x, f1, f2, bias, out);
}

// round 5
// speedup vs baseline: 2.6590x; 2.6590x over previous
#include <cuda_runtime.h>
#include <cuda_fp16.h>
#include <cstdint>

// x: [16384,1024] fp32 rows, groups of 16 tokens (G=1024 groups)
// ctrl[d*64+es], f1[d*4096+es*64+f], f2[es*65536+f*1024+d], bias[es*64+f]
// out[16384,1024] fp32, sum of 64 (e,s) contributions.

#define AP 70

__device__ int    g_sel[1024 * 64];        // selected token per (group, es)
__device__ __half g_w1h[64 * 64 * 1024];   // [es][f][d] fp16
__device__ __half g_w2h[64 * 1024 * 64];   // [es][d][f] fp16

// ======================= helpers =======================
__device__ __forceinline__ uint32_t smem_u32(const void* p) {
    uint32_t a;
    asm("{ .reg .u64 t; cvta.to.shared.u64 t, %1; cvt.u32.u64 %0, t; }" : "=r"(a) : "l"(p));
    return a;
}
#define SWZ(b) ((b) ^ (((b) >> 3) & 0x70))

__device__ __forceinline__ void sts64(uint32_t a, uint32_t x, uint32_t y) {
    asm volatile("st.shared.v2.b32 [%0], {%1,%2};" :: "r"(a), "r"(x), "r"(y) : "memory");
}
__device__ __forceinline__ void sts128(uint32_t a, uint32_t x, uint32_t y, uint32_t z, uint32_t w) {
    asm volatile("st.shared.v4.b32 [%0], {%1,%2,%3,%4};" :: "r"(a), "r"(x), "r"(y), "r"(z), "r"(w) : "memory");
}
__device__ __forceinline__ void sts32(uint32_t a, uint32_t x) {
    asm volatile("st.shared.b32 [%0], %1;" :: "r"(a), "r"(x) : "memory");
}

#define LDSM4(r, addr) \
    asm volatile("ldmatrix.sync.aligned.m8n8.x4.shared.b16 {%0,%1,%2,%3}, [%4];" \
                 : "=r"((r)[0]), "=r"((r)[1]), "=r"((r)[2]), "=r"((r)[3]) : "r"(addr))

#define MMA16816(d, a, b0, b1) \
    asm volatile("mma.sync.aligned.m16n8k16.row.col.f32.f16.f16.f32 " \
                 "{%0,%1,%2,%3}, {%4,%5,%6,%7}, {%8,%9}, {%0,%1,%2,%3};" \
                 : "+f"((d)[0]), "+f"((d)[1]), "+f"((d)[2]), "+f"((d)[3]) \
                 : "r"((a)[0]), "r"((a)[1]), "r"((a)[2]), "r"((a)[3]), "r"(b0), "r"(b1))

__device__ __forceinline__ void red_v4(float* p, float4 v) {
    asm volatile("red.global.add.v4.f32 [%0], {%1,%2,%3,%4};"
                 :: "l"(p), "f"(v.x), "f"(v.y), "f"(v.z), "f"(v.w) : "memory");
}

__device__ __forceinline__ uint32_t pack_h2(float lo, float hi) {
    __half2 h = __floats2half2_rn(lo, hi);
    return *(uint32_t*)&h;
}

__device__ __forceinline__ unsigned long long ffma2(unsigned long long a, unsigned long long b, unsigned long long c) {
    unsigned long long d;
    asm("fma.rn.f32x2 %0, %1, %2, %3;" : "=l"(d) : "l"(a), "l"(b), "l"(c));
    return d;
}
__device__ __forceinline__ float2 unpack2(unsigned long long v) {
    float2 r; asm("mov.b64 {%0, %1}, %2;" : "=f"(r.x), "=f"(r.y) : "l"(v)); return r;
}

// ======================= kernel 0: zero out =======================
__global__ void k_zero(float4* __restrict__ out, int n4) {
    int i = blockIdx.x * blockDim.x + threadIdx.x;
    int stride = gridDim.x * blockDim.x;
    for (; i < n4; i += stride) out[i] = make_float4(0.f, 0.f, 0.f, 0.f);
}

// ======================= prep: fp16 weight transposes =======================
__global__ __launch_bounds__(256) void k_prep_w1(const float* __restrict__ f1) {
    __shared__ float t[32][33];
    int d0 = blockIdx.x * 32, es = blockIdx.y, f0 = blockIdx.z * 32;
    int tx = threadIdx.x & 31, ty = threadIdx.x >> 5;
#pragma unroll
    for (int p = 0; p < 4; p++)
        t[ty + p * 8][tx] = f1[(d0 + ty + p * 8) * 4096 + es * 64 + f0 + tx];
    __syncthreads();
#pragma unroll
    for (int p = 0; p < 4; p++) {
        int fl = ty + p * 8;
        g_w1h[es * 65536 + (f0 + fl) * 1024 + d0 + tx] = __float2half(t[tx][fl]);
    }
}

__global__ __launch_bounds__(256) void k_prep_w2(const float* __restrict__ f2) {
    __shared__ float t[32][33];
    int d0 = blockIdx.x * 32, es = blockIdx.y, f0 = blockIdx.z * 32;
    int tx = threadIdx.x & 31, ty = threadIdx.x >> 5;
#pragma unroll
    for (int p = 0; p < 4; p++)
        t[ty + p * 8][tx] = f2[es * 65536 + (f0 + ty + p * 8) * 1024 + d0 + tx];
    __syncthreads();
#pragma unroll
    for (int p = 0; p < 4; p++) {
        int dl = ty + p * 8;
        g_w2h[es * 65536 + (d0 + dl) * 64 + f0 + tx] = __float2half(t[tx][dl]);
    }
}

// ======================= kernel 1: router (exact fp32) =======================
__global__ __launch_bounds__(256) void k_router(const float* __restrict__ x,
                                                const float* __restrict__ ctrl) {
    __shared__ __align__(16) float As[64 * AP];
    __shared__ __align__(16) float Bs[64 * AP];
    const int tid = threadIdx.x;
    const int rt = tid & 15;
    const int ct = tid >> 4;
    const int m0 = blockIdx.x * 64;

    unsigned long long acc[4][4];
#pragma unroll
    for (int i = 0; i < 4; i++)
#pragma unroll
        for (int j = 0; j < 4; j++) acc[i][j] = 0ull;

    for (int kc = 0; kc < 1024; kc += 64) {
#pragma unroll
        for (int q = 0; q < 4; q++) {
            int id = tid + 256 * q;
            int r = id >> 4;
            int k4 = (id & 15) << 2;
            float4 v = *(const float4*)(x + (m0 + r) * 1024 + kc + k4);
            float* dst = As + r * AP + k4;
            *(float2*)dst = make_float2(v.x, v.y);
            *(float2*)(dst + 2) = make_float2(v.z, v.w);
        }
#pragma unroll
        for (int q = 0; q < 4; q++) {
            int id = tid + 256 * q;
            int k = id >> 4;
            int e4 = (id & 15) << 2;
            float4 v = *(const float4*)(ctrl + (kc + k) * 64 + e4);
            Bs[(e4 + 0) * AP + k] = v.x;
            Bs[(e4 + 1) * AP + k] = v.y;
            Bs[(e4 + 2) * AP + k] = v.z;
            Bs[(e4 + 3) * AP + k] = v.w;
        }
        __syncthreads();
#pragma unroll
        for (int k = 0; k < 64; k += 2) {
            unsigned long long a[4], b[4];
#pragma unroll
            for (int i = 0; i < 4; i++)
                a[i] = *(const unsigned long long*)(As + (rt + 16 * i) * AP + k);
#pragma unroll
            for (int j = 0; j < 4; j++)
                b[j] = *(const unsigned long long*)(Bs + (ct + 16 * j) * AP + k);
#pragma unroll
            for (int i = 0; i < 4; i++)
#pragma unroll
                for (int j = 0; j < 4; j++) acc[i][j] = ffma2(a[i], b[j], acc[i][j]);
        }
        __syncthreads();
    }

    const float tie = (float)((double)rt * (1e-6 / 15.0));
#pragma unroll
    for (int i = 0; i < 4; i++) {
#pragma unroll
        for (int j = 0; j < 4; j++) {
            float2 p = unpack2(acc[i][j]);
            float v = p.x + p.y + tie;
            int t = rt;
#pragma unroll
            for (int m = 8; m >= 1; m >>= 1) {
                float ov = __shfl_xor_sync(0xffffffffu, v, m);
                int ot = __shfl_xor_sync(0xffffffffu, t, m);
                if (ov > v || (ov == v && ot > t)) { v = ov; t = ot; }
            }
            if (rt == 0) g_sel[(blockIdx.x * 4 + i) * 64 + (ct + 16 * j)] = t;
        }
    }
}

// ======================= kernel 2: HMMA fp16 FFN =======================
// grid (8 m-tiles of 128 groups, 64 es), 256 threads / 8 warps (4M x 2N).
// Phase1: H[128x64] = relu(Xsel[128x1024] @ W1^T + b)  (16 K-chunks of 64)
// Phase2: Z[128x1024] = H @ W2^T in 16 n-chunks of 64, red.v4 scatter-add.
__global__ __launch_bounds__(256, 2) void k_ffn(const float* __restrict__ x,
                                                const float* __restrict__ bias,
                                                float* __restrict__ out) {
    extern __shared__ char dsm[];
    __shared__ int selrow[128];
    __shared__ float biasS[64];

    const int tid = threadIdx.x;
    const int lane = tid & 31;
    const int wid = tid >> 5;
    const int mw = wid >> 1;      // 0..3 (M)
    const int nw = wid & 1;       // 0..1 (N)
    const int es = blockIdx.y;
    const int g0 = blockIdx.x * 128;

    const uint32_t smemu = smem_u32(dsm);
    const uint32_t base = (smemu + 1023) & ~1023u;
    const uint32_t HsB = base;               // 16KB  H [128][64] halves
    const uint32_t A1B = base + 16384;       // 2 x 16KB (phase1 A)
    const uint32_t B1B = base + 49152;       // 2 x 8KB  (phase1 B)
    const uint32_t B2B = base + 16384;       // 2 x 8KB  (phase2 B)
    float* Zs = (float*)(dsm + (base - smemu) + 32768);  // [128][68] f32

    if (tid < 128) { int t = g_sel[(g0 + tid) * 64 + es]; selrow[tid] = (g0 + tid) * 16 + t; }
    if (tid < 64) biasS[tid] = bias[es * 64 + tid];
    __syncthreads();

    // ---------------- Phase 1 ----------------
    const int r0 = tid >> 4;            // A-stage row base
    const int k4 = (tid & 15) << 2;     // A-stage k (floats)
    const int fB = tid >> 3;            // B-stage row base
    const int k16 = (tid & 7) << 3;     // B-stage k (halves)

    float acc1[2][4][4];
#pragma unroll
    for (int mi = 0; mi < 2; mi++)
#pragma unroll
        for (int nj = 0; nj < 4; nj++)
#pragma unroll
            for (int e = 0; e < 4; e++) acc1[mi][nj][e] = 0.f;

    float4 av[8];
    uint4 bv[2];
    // prolog: load chunk 0
#pragma unroll
    for (int q = 0; q < 8; q++)
        av[q] = *(const float4*)(x + (size_t)selrow[q * 16 + r0] * 1024 + k4);
#pragma unroll
    for (int q = 0; q < 2; q++)
        bv[q] = *(const uint4*)(g_w1h + (size_t)es * 65536 + (q * 32 + fB) * 1024 + k16);

    for (int c = 0; c < 16; c++) {
        const int b = c & 1;
        const uint32_t aB = A1B + b * 16384;
        const uint32_t bB = B1B + b * 8192;
        // stage
#pragma unroll
        for (int q = 0; q < 8; q++) {
            uint32_t byte = (q * 16 + r0) * 128 + (k4 << 1);
            sts64(aB + SWZ(byte), pack_h2(av[q].x, av[q].y), pack_h2(av[q].z, av[q].w));
        }
#pragma unroll
        for (int q = 0; q < 2; q++) {
            uint32_t byte = (q * 32 + fB) * 128 + (k16 << 1);
            sts128(bB + SWZ(byte), bv[q].x, bv[q].y, bv[q].z, bv[q].w);
        }
        __syncthreads();
        // prefetch next chunk
        if (c < 15) {
            const int kc = (c + 1) * 64;
#pragma unroll
            for (int q = 0; q < 8; q++)
                av[q] = *(const float4*)(x + (size_t)selrow[q * 16 + r0] * 1024 + kc + k4);
#pragma unroll
            for (int q = 0; q < 2; q++)
                bv[q] = *(const uint4*)(g_w1h + (size_t)es * 65536 + (q * 32 + fB) * 1024 + kc + k16);
        }
        // mma
#pragma unroll
        for (int ks = 0; ks < 4; ks++) {
            uint32_t af[2][4], bf[2][4];
#pragma unroll
            for (int mi = 0; mi < 2; mi++) {
                uint32_t byte = (mw * 32 + mi * 16 + (lane & 15)) * 128 + ks * 32 + ((lane >> 4) << 4);
                LDSM4(af[mi], aB + SWZ(byte));
            }
#pragma unroll
            for (int ni = 0; ni < 2; ni++) {
                uint32_t byte = (nw * 32 + ni * 16 + (lane & 15)) * 128 + ks * 32 + ((lane >> 4) << 4);
                LDSM4(bf[ni], bB + SWZ(byte));
            }
#pragma unroll
            for (int mi = 0; mi < 2; mi++)
#pragma unroll
                for (int nj = 0; nj < 4; nj++)
                    MMA16816(acc1[mi][nj], af[mi], bf[nj >> 1][nj & 1], bf[nj >> 1][(nj & 1) + 2]);
        }
    }

    // epilogue: bias + relu -> fp16 H in smem
#pragma unroll
    for (int mi = 0; mi < 2; mi++) {
        const int rA = mw * 32 + mi * 16 + (lane >> 2);
#pragma unroll
        for (int nj = 0; nj < 4; nj++) {
            const int cb = nw * 32 + nj * 8 + ((lane & 3) << 1);
            float b0 = biasS[cb], b1 = biasS[cb + 1];
            uint32_t lo = pack_h2(fmaxf(acc1[mi][nj][0] + b0, 0.f), fmaxf(acc1[mi][nj][1] + b1, 0.f));
            uint32_t hi = pack_h2(fmaxf(acc1[mi][nj][2] + b0, 0.f), fmaxf(acc1[mi][nj][3] + b1, 0.f));
            sts32(HsB + SWZ((uint32_t)(rA * 128 + cb * 2)), lo);
            sts32(HsB + SWZ((uint32_t)((rA + 8) * 128 + cb * 2)), hi);
        }
    }
    __syncthreads();

    // ---------------- Phase 2 ----------------
    uint4 bv2[2];
#pragma unroll
    for (int q = 0; q < 2; q++)
        bv2[q] = *(const uint4*)(g_w2h + (size_t)es * 65536 + (size_t)(q * 32 + fB) * 64 + k16);

    for (int nc = 0; nc < 16; nc++) {
        const int b = nc & 1;
        const uint32_t bB = B2B + b * 8192;
#pragma unroll
        for (int q = 0; q < 2; q++) {
            uint32_t byte = (q * 32 + fB) * 128 + (k16 << 1);
            sts128(bB + SWZ(byte), bv2[q].x, bv2[q].y, bv2[q].z, bv2[q].w);
        }
        __syncthreads();
        if (nc < 15) {
#pragma unroll
            for (int q = 0; q < 2; q++)
                bv2[q] = *(const uint4*)(g_w2h + (size_t)es * 65536 +
                                         (size_t)((nc + 1) * 64 + q * 32 + fB) * 64 + k16);
        }

        float acc2[2][4][4];
#pragma unroll
        for (int mi = 0; mi < 2; mi++)
#pragma unroll
            for (int nj = 0; nj < 4; nj++)
#pragma unroll
                for (int e = 0; e < 4; e++) acc2[mi][nj][e] = 0.f;

#pragma unroll
        for (int ks = 0; ks < 4; ks++) {
            uint32_t af[2][4], bf[2][4];
#pragma unroll
            for (int mi = 0; mi < 2; mi++) {
                uint32_t byte = (mw * 32 + mi * 16 + (lane & 15)) * 128 + ks * 32 + ((lane >> 4) << 4);
                LDSM4(af[mi], HsB + SWZ(byte));
            }
#pragma unroll
            for (int ni = 0; ni < 2; ni++) {
                uint32_t byte = (nw * 32 + ni * 16 + (lane & 15)) * 128 + ks * 32 + ((lane >> 4) << 4);
                LDSM4(bf[ni], bB + SWZ(byte));
            }
#pragma unroll
            for (int mi = 0; mi < 2; mi++)
#pragma unroll
                for (int nj = 0; nj < 4; nj++)
                    MMA16816(acc2[mi][nj], af[mi], bf[nj >> 1][nj & 1], bf[nj >> 1][(nj & 1) + 2]);
        }

        // stage Z and vector-RED to out
#pragma unroll
        for (int mi = 0; mi < 2; mi++) {
            const int rA = mw * 32 + mi * 16 + (lane >> 2);
#pragma unroll
            for (int nj = 0; nj < 4; nj++) {
                const int cb = nw * 32 + nj * 8 + ((lane & 3) << 1);
                *(float2*)(Zs + rA * 68 + cb) = make_float2(acc2[mi][nj][0], acc2[mi][nj][1]);
                *(float2*)(Zs + (rA + 8) * 68 + cb) = make_float2(acc2[mi][nj][2], acc2[mi][nj][3]);
            }
        }
        __syncthreads();
#pragma unroll
        for (int q = 0; q < 8; q++) {
            int s = q * 256 + tid;
            int row = s >> 4;
            int c4 = (s & 15) << 2;
            float4 v = *(const float4*)(Zs + row * 68 + c4);
            red_v4(out + (size_t)selrow[row] * 1024 + nc * 64 + c4, v);
        }
        __syncthreads();
    }
}

// ======================= launch =======================
extern "C" void kernel_launch(void* const* d_in, const int* in_sizes, int n_in,
                              void* d_out, int out_size) {
    const float* x    = (const float*)d_in[0];
    const float* ctrl = (const float*)d_in[1];
    const float* f1   = (const float*)d_in[2];
    const float* f2   = (const float*)d_in[3];
    const float* bias = (const float*)d_in[4];
    float* out = (float*)d_out;

    cudaFuncSetAttribute(k_ffn, cudaFuncAttributeMaxDynamicSharedMemorySize, 69632);

    k_zero<<<2048, 256>>>((float4*)out, out_size / 4);
    k_prep_w1<<<dim3(32, 64, 2), 256>>>(f1);
    k_prep_w2<<<dim3(32, 64, 2), 256>>>(f2);
    k_router<<<256, 256>>>(x, ctrl);
    k_ffn<<<dim3(8, 64), 256, 69632>>>(x, bias, out);
}